// round 10
// baseline (speedup 1.0000x reference)
#include <cuda_runtime.h>

#define TJ 128          // j-tile = block threads
#define ITILE 4         // i-rows per thread
#define TI (TJ * ITILE) // 512: i-tile span
#define MAXN 8192
#define NBINS 64
#define MAX_BLOCKS 8192

__device__ float4 g_sorted[MAXN];     // atoms sorted by z: {x,y,z,q}
__device__ float  g_partials[MAX_BLOCKS];
__device__ int    g_counter = 0;      // self-resetting arrival counter

// fs(d2) = 1 + s^2 * P(s), P(s) = A + B s + C s^2 + D s^3, s = sat((d2-9)/16)
// P(1) = -1 exactly -> fs == 0 for d2 >= 25 (far-block skip is EXACT).
#define FS_A  1.733f
#define FS_B  (-23.203f)
#define FS_C  38.001f
#define FS_D  (-17.531f)

// ---------------- deterministic stable counting sort by z ----------------
__global__ __launch_bounds__(1024)
void sort_kernel(const float* __restrict__ q, const float* __restrict__ xyz, int n) {
    __shared__ int hist[NBINS];
    __shared__ int binStart[NBINS];
    __shared__ int runTot[NBINS];
    __shared__ int warpCnt[32][NBINS];
    const int t = threadIdx.x;
    const int warp = t >> 5, lane = t & 31;
    if (t < NBINS) { hist[t] = 0; runTot[t] = 0; }
    __syncthreads();
    for (int base = 0; base < n; base += 1024) {
        int i = base + t;
        if (i < n) {
            float z = xyz[3 * i + 2];
            int b = (int)(z * (NBINS / 40.0f));
            b = min(max(b, 0), NBINS - 1);
            atomicAdd(&hist[b], 1);            // counts: order-independent
        }
    }
    __syncthreads();
    if (t == 0) {
        int acc = 0;
        for (int b = 0; b < NBINS; b++) { binStart[b] = acc; acc += hist[b]; }
    }
    __syncthreads();
    for (int base = 0; base < n; base += 1024) {
        for (int idx = t; idx < 32 * NBINS; idx += 1024)
            ((int*)warpCnt)[idx] = 0;
        __syncthreads();
        int i = base + t;
        int b = -1;
        float x = 0.f, y = 0.f, z = 0.f, w = 0.f;
        if (i < n) {
            x = xyz[3 * i]; y = xyz[3 * i + 1]; z = xyz[3 * i + 2]; w = q[i];
            b = (int)(z * (NBINS / 40.0f));
            b = min(max(b, 0), NBINS - 1);
        }
        unsigned mm = __match_any_sync(0xFFFFFFFFu, b);
        int rk = __popc(mm & ((1u << lane) - 1u));   // stable intra-warp rank
        if (b >= 0 && rk == 0)                       // leader (lowest lane of group)
            warpCnt[warp][b] = __popc(mm);
        __syncthreads();
        if (t < NBINS) {                             // cross-warp exclusive scan per bin
            int acc = runTot[t];
            for (int w2 = 0; w2 < 32; w2++) {
                int v = warpCnt[w2][t];
                warpCnt[w2][t] = acc;
                acc += v;
            }
            runTot[t] = acc;
        }
        __syncthreads();
        if (i < n) {
            int dst = binStart[b] + warpCnt[warp][b] + rk;
            g_sorted[dst] = make_float4(x, y, z, w);
        }
        __syncthreads();
    }
}

// ---------------- pair kernels ----------------

// Branchless full term (diagonal rows only).
__device__ __forceinline__ float term_d2(float d2) {
    float rinv = rsqrtf(d2);
    float s = __saturatef(fmaf(d2, 0.0625f, -0.5625f));
    float w = fmaf(fmaf(fmaf(FS_D, s, FS_C), s, FS_B), s, FS_A);
    float u = s * s;
    float isq = rsqrtf(d2 + 1.0f);
    float g = isq - rinv;
    float fs = fmaf(u, w, 1.0f);
    return fmaf(fs, g, rinv);
}

// Far block: bare Coulomb only (correction is exactly 0).
#define FARPAIR(m)                                                            \
    {                                                                         \
        float d2 = fmaf(nz##m, p.z, fmaf(ny##m, p.y,                          \
                     fmaf(nx##m, p.x, Ri##m + Rj)));                          \
        acc##m = fmaf(p.w, rsqrtf(d2), acc##m);                               \
    }

// Near block: bare Coulomb + warp-uniform rare correction.
#define PAIR(m)                                                               \
    {                                                                         \
        float d2 = fmaf(nz##m, p.z, fmaf(ny##m, p.y,                          \
                     fmaf(nx##m, p.x, Ri##m + Rj)));                          \
        float rinv = rsqrtf(d2);                                              \
        acc##m = fmaf(p.w, rinv, acc##m);                                     \
        if (__any_sync(0xFFFFFFFFu, d2 < 25.0f)) {                            \
            float s = __saturatef(fmaf(d2, 0.0625f, -0.5625f));               \
            float w = fmaf(fmaf(fmaf(FS_D, s, FS_C), s, FS_B), s, FS_A);      \
            float u = s * s;                                                  \
            float fsw = u * w;                                                \
            float isq = rsqrtf(d2 + 1.0f);                                    \
            float g = isq - rinv;                                             \
            float corr = fmaf(fsw, g, g);                                     \
            acc##m = fmaf(p.w, corr, acc##m);                                 \
        }                                                                     \
    }

__global__ __launch_bounds__(TJ)
void elec_pair_kernel(float* __restrict__ out,
                      int n, int jT, int iT, int nBlocks) {
    // Ordering by diagonal distance d = J - ITILE*I, ascending (near blocks first).
    const int bid = blockIdx.x;
    int d = 0, s = 0;
    for (;;) {
        int cnt = (jT - 1 - d) / ITILE + 1;
        if (cnt > iT) cnt = iT;
        if (cnt < 1) cnt = 1;                 // defensive; host uses same formula
        if (bid < s + cnt) break;
        s += cnt; d++;
    }
    const int I = bid - s;
    const int J = ITILE * I + d;
    const int c = d;                  // < ITILE: partial/diagonal; >= ITILE: full

    const int t = threadIdx.x;
    __shared__ float4 tile[TJ];
    __shared__ float  tileR[TJ];
    __shared__ float  warpsum[TJ / 32];
    __shared__ int    lastFlag;

    // Stage j-tile from sorted atoms.
    {
        const int jg = J * TJ + t;
        float4 p4 = (jg < n) ? g_sorted[jg]
                             : make_float4(1.0e6f + (float)t * 64.0f, 0.f, 0.f, 0.f);
        tile[t]  = p4;
        tileR[t] = fmaf(p4.x, p4.x, fmaf(p4.y, p4.y, p4.z * p4.z));
    }
    __syncthreads();

    // Four i-rows per thread (coalesced float4 loads from sorted array).
    const int ib = I * TI + t;
    float nx0, ny0, nz0, Ri0, qi0, nx1, ny1, nz1, Ri1, qi1;
    float nx2, ny2, nz2, Ri2, qi2, nx3, ny3, nz3, Ri3, qi3;
    {
        #define LOADI(m, ig)                                                      \
            { float4 a = ((ig) < n) ? g_sorted[(ig)]                              \
                  : make_float4(2.0e6f + (float)(ig) * 64.0f, 0.f, 0.f, 0.f);     \
              nx##m = -2.0f * a.x; ny##m = -2.0f * a.y; nz##m = -2.0f * a.z;      \
              Ri##m = fmaf(a.x, a.x, fmaf(a.y, a.y, a.z * a.z));                  \
              qi##m = a.w; }
        LOADI(0, ib) LOADI(1, ib + TJ) LOADI(2, ib + 2 * TJ) LOADI(3, ib + 3 * TJ)
        #undef LOADI
    }

    float acc0 = 0.0f, acc1 = 0.0f, acc2 = 0.0f, acc3 = 0.0f, accD = 0.0f;

    if (c >= ITILE) {
        // z-gap classification: j-tile entirely after i-tile in sorted order.
        int iLast  = min(I * TI + TI, n) - 1;
        int jFirst = min(J * TJ, n - 1);
        bool nearBlk = (g_sorted[jFirst].z - g_sorted[iLast].z) < 5.0f;
        if (!nearBlk) {
            #pragma unroll 4
            for (int k = 0; k < TJ; k++) {
                float4 p = tile[k]; float Rj = tileR[k];
                FARPAIR(0) FARPAIR(1) FARPAIR(2) FARPAIR(3)
            }
        } else {
            #pragma unroll 4
            for (int k = 0; k < TJ; k++) {
                float4 p = tile[k]; float Rj = tileR[k];
                PAIR(0) PAIR(1) PAIR(2) PAIR(3)
            }
        }
    } else {
        // Partial: rows m < c full (near by construction), row c diagonal.
        if (c == 3) {
            #pragma unroll 4
            for (int k = 0; k < TJ; k++) {
                float4 p = tile[k]; float Rj = tileR[k];
                PAIR(0) PAIR(1) PAIR(2)
            }
        } else if (c == 2) {
            #pragma unroll 4
            for (int k = 0; k < TJ; k++) {
                float4 p = tile[k]; float Rj = tileR[k];
                PAIR(0) PAIR(1)
            }
        } else if (c == 1) {
            #pragma unroll 4
            for (int k = 0; k < TJ; k++) {
                float4 p = tile[k]; float Rj = tileR[k];
                PAIR(0)
            }
        }
        // Diagonal row c (lane-dependent trip count -> branchless term).
        float nxd = (c == 0) ? nx0 : (c == 1) ? nx1 : (c == 2) ? nx2 : nx3;
        float nyd = (c == 0) ? ny0 : (c == 1) ? ny1 : (c == 2) ? ny2 : ny3;
        float nzd = (c == 0) ? nz0 : (c == 1) ? nz1 : (c == 2) ? nz2 : nz3;
        float Rid = (c == 0) ? Ri0 : (c == 1) ? Ri1 : (c == 2) ? Ri2 : Ri3;
        for (int k = t + 1; k < TJ; k++) {
            float4 p = tile[k];
            float Rj = tileR[k];
            float d2 = fmaf(nzd, p.z, fmaf(nyd, p.y, fmaf(nxd, p.x, Rid + Rj)));
            accD = fmaf(p.w, term_d2(d2), accD);
        }
    }

    float qd = (c >= ITILE) ? 0.0f : (c == 0) ? qi0 : (c == 1) ? qi1 : (c == 2) ? qi2 : qi3;
    float accT = qi0 * acc0 + qi1 * acc1 + qi2 * acc2 + qi3 * acc3 + qd * accD;

    // Block reduction.
    #pragma unroll
    for (int off = 16; off > 0; off >>= 1)
        accT += __shfl_down_sync(0xFFFFFFFFu, accT, off);
    if ((t & 31) == 0) warpsum[t >> 5] = accT;
    __syncthreads();

    if (t == 0) {
        float sum = 0.0f;
        #pragma unroll
        for (int w = 0; w < TJ / 32; w++) sum += warpsum[w];
        g_partials[bid] = sum;
        __threadfence();
        int ticket = atomicAdd(&g_counter, 1);
        lastFlag = (ticket == nBlocks - 1) ? 1 : 0;
    }
    __syncthreads();

    if (lastFlag) {
        float a2 = 0.0f;
        for (int i = t; i < nBlocks; i += TJ)
            a2 += g_partials[i];
        #pragma unroll
        for (int off = 16; off > 0; off >>= 1)
            a2 += __shfl_down_sync(0xFFFFFFFFu, a2, off);
        if ((t & 31) == 0) warpsum[t >> 5] = a2;
        __syncthreads();
        if (t == 0) {
            float sum = 0.0f;
            #pragma unroll
            for (int w = 0; w < TJ / 32; w++) sum += warpsum[w];
            out[0] = sum * 332.0637f;   // KE_KCAL once
            g_counter = 0;              // reset for next graph replay
        }
    }
}

extern "C" void kernel_launch(void* const* d_in, const int* in_sizes, int n_in,
                              void* d_out, int out_size) {
    const float* q   = (const float*)d_in[0];
    const float* xyz = (const float*)d_in[1];
    float* out = (float*)d_out;

    int n = in_sizes[0];
    if (n > MAXN) n = MAXN;
    int jT = (n + TJ - 1) / TJ;
    int iT = (n + TI - 1) / TI;

    int nBlocks = 0;
    for (int d = 0; d < jT; d++) {
        int cnt = (jT - 1 - d) / ITILE + 1;
        if (cnt > iT) cnt = iT;
        if (cnt < 1) cnt = 1;
        nBlocks += cnt;
    }
    if (nBlocks > MAX_BLOCKS) nBlocks = MAX_BLOCKS;

    sort_kernel<<<1, 1024>>>(q, xyz, n);
    elec_pair_kernel<<<nBlocks, TJ>>>(out, n, jT, iT, nBlocks);
}

// round 11
// speedup vs baseline: 1.4343x; 1.4343x over previous
#include <cuda_runtime.h>

#define TJ 128          // j-tile = block threads
#define ITILE 2         // i-rows per thread
#define TI (TJ * ITILE) // 256: i-tile span
#define MAXN 8192
#define NBINS 64
#define CHUNK 256       // atoms per sort block
#define MAXCHUNK (MAXN / CHUNK)
#define MAX_BLOCKS 8192

__device__ float4 g_sorted[MAXN];
__device__ int    g_cnt[MAXCHUNK * NBINS];
__device__ int    g_off[MAXCHUNK * NBINS];
__device__ int    g_rank[MAXN];
__device__ float  g_partials[MAX_BLOCKS];
__device__ int    g_counter = 0;

// fs(d2) = 1 + s^2 * P(s), P(s)=A+Bs+Cs^2+Ds^3, s = sat((d2-9)/16)
// P(1) = -1 exactly -> fs == 0 for d2 >= 25 (far skip EXACT).
#define FS_A  1.733f
#define FS_B  (-23.203f)
#define FS_C  38.001f
#define FS_D  (-17.531f)

__device__ __forceinline__ int zbin(float z) {
    int b = (int)(z * (NBINS / 40.0f));
    return min(max(b, 0), NBINS - 1);
}

// ---- sort A: per-chunk bin counts + stable intra-chunk ranks ----
__global__ __launch_bounds__(CHUNK)
void sortA(const float* __restrict__ xyz, int n) {
    const int blk = blockIdx.x, t = threadIdx.x;
    const int i = blk * CHUNK + t;
    const int warp = t >> 5, lane = t & 31;
    __shared__ int warpCnt[CHUNK / 32][NBINS];
    __shared__ int warpBase[CHUNK / 32][NBINS];
    for (int k = t; k < (CHUNK / 32) * NBINS; k += CHUNK)
        ((int*)warpCnt)[k] = 0;
    __syncthreads();
    int b = -1;
    if (i < n) b = zbin(xyz[3 * i + 2]);
    unsigned mm = __match_any_sync(0xFFFFFFFFu, b);
    int rk = __popc(mm & ((1u << lane) - 1u));
    if (b >= 0 && rk == 0) warpCnt[warp][b] = __popc(mm);
    __syncthreads();
    if (t < NBINS) {
        int acc = 0;
        #pragma unroll
        for (int w = 0; w < CHUNK / 32; w++) { warpBase[w][t] = acc; acc += warpCnt[w][t]; }
        g_cnt[blk * NBINS + t] = acc;
    }
    __syncthreads();
    if (i < n) g_rank[i] = warpBase[warp][b] + rk;
}

// ---- sort B: global offsets (1 block, 64 threads) ----
__global__ __launch_bounds__(NBINS)
void sortB(int nChunks) {
    const int b = threadIdx.x;
    __shared__ int binTot[NBINS];
    __shared__ int binStart[NBINS];
    int acc = 0;
    for (int blk = 0; blk < nChunks; blk++) {
        g_off[blk * NBINS + b] = acc;
        acc += g_cnt[blk * NBINS + b];
    }
    binTot[b] = acc;
    __syncthreads();
    if (b == 0) {
        int s = 0;
        for (int k = 0; k < NBINS; k++) { binStart[k] = s; s += binTot[k]; }
    }
    __syncthreads();
    int s = binStart[b];
    for (int blk = 0; blk < nChunks; blk++)
        g_off[blk * NBINS + b] += s;
}

// ---- sort C: scatter ----
__global__ __launch_bounds__(CHUNK)
void sortC(const float* __restrict__ q, const float* __restrict__ xyz, int n) {
    const int blk = blockIdx.x, t = threadIdx.x;
    const int i = blk * CHUNK + t;
    if (i < n) {
        float x = xyz[3 * i], y = xyz[3 * i + 1], z = xyz[3 * i + 2], w = q[i];
        int b = zbin(z);
        g_sorted[g_off[blk * NBINS + b] + g_rank[i]] = make_float4(x, y, z, w);
    }
}

// ---- pair kernel ----
__device__ __forceinline__ float term_d2(float d2) {
    float rinv = rsqrtf(d2);
    float s = __saturatef(fmaf(d2, 0.0625f, -0.5625f));
    float w = fmaf(fmaf(fmaf(FS_D, s, FS_C), s, FS_B), s, FS_A);
    float u = s * s;
    float isq = rsqrtf(d2 + 1.0f);
    float g = isq - rinv;
    float fs = fmaf(u, w, 1.0f);
    return fmaf(fs, g, rinv);
}

#define FARPAIR(m)                                                            \
    {                                                                         \
        float d2 = fmaf(nz##m, p.z, fmaf(ny##m, p.y,                          \
                     fmaf(nx##m, p.x, Ri##m + Rj)));                          \
        acc##m = fmaf(p.w, rsqrtf(d2), acc##m);                               \
    }

#define PAIR(m)                                                               \
    {                                                                         \
        float d2 = fmaf(nz##m, p.z, fmaf(ny##m, p.y,                          \
                     fmaf(nx##m, p.x, Ri##m + Rj)));                          \
        float rinv = rsqrtf(d2);                                              \
        acc##m = fmaf(p.w, rinv, acc##m);                                     \
        if (__any_sync(0xFFFFFFFFu, d2 < 25.0f)) {                            \
            float s = __saturatef(fmaf(d2, 0.0625f, -0.5625f));               \
            float w = fmaf(fmaf(fmaf(FS_D, s, FS_C), s, FS_B), s, FS_A);      \
            float u = s * s;                                                  \
            float fsw = u * w;                                                \
            float isq = rsqrtf(d2 + 1.0f);                                    \
            float g = isq - rinv;                                             \
            float corr = fmaf(fsw, g, g);                                     \
            acc##m = fmaf(p.w, corr, acc##m);                                 \
        }                                                                     \
    }

__global__ __launch_bounds__(TJ)
void elec_pair_kernel(float* __restrict__ out,
                      int n, int jT, int iT, int nBlocks) {
    // Near-diagonal-first: d = J - ITILE*I ascending.
    const int bid = blockIdx.x;
    int d = 0, s = 0;
    for (;;) {
        int cnt = (jT - 1 - d) / ITILE + 1;
        if (cnt > iT) cnt = iT;
        if (cnt < 1) cnt = 1;
        if (bid < s + cnt) break;
        s += cnt; d++;
    }
    const int I = bid - s;
    const int J = ITILE * I + d;
    const int c = d;                  // < ITILE: partial/diag; >= ITILE: full

    const int t = threadIdx.x;
    __shared__ float4 tile[TJ];
    __shared__ float  tileR[TJ];
    __shared__ float  warpsum[TJ / 32];
    __shared__ int    lastFlag;

    {
        const int jg = J * TJ + t;
        float4 p4 = (jg < n) ? g_sorted[jg]
                             : make_float4(1.0e6f + (float)t * 64.0f, 0.f, 0.f, 0.f);
        tile[t]  = p4;
        tileR[t] = fmaf(p4.x, p4.x, fmaf(p4.y, p4.y, p4.z * p4.z));
    }
    __syncthreads();

    const int ib = I * TI + t;
    float nx0, ny0, nz0, Ri0, qi0, nx1, ny1, nz1, Ri1, qi1;
    {
        #define LOADI(m, ig)                                                      \
            { float4 a = ((ig) < n) ? g_sorted[(ig)]                              \
                  : make_float4(2.0e6f + (float)(ig) * 64.0f, 0.f, 0.f, 0.f);     \
              nx##m = -2.0f * a.x; ny##m = -2.0f * a.y; nz##m = -2.0f * a.z;      \
              Ri##m = fmaf(a.x, a.x, fmaf(a.y, a.y, a.z * a.z));                  \
              qi##m = a.w; }
        LOADI(0, ib) LOADI(1, ib + TJ)
        #undef LOADI
    }

    float acc0 = 0.0f, acc1 = 0.0f, accD = 0.0f;

    if (c >= ITILE) {
        int iLast  = min(I * TI + TI, n) - 1;
        int jFirst = min(J * TJ, n - 1);
        bool nearBlk = (g_sorted[jFirst].z - g_sorted[iLast].z) < 5.0f;
        if (!nearBlk) {
            #pragma unroll 4
            for (int k = 0; k < TJ; k++) {
                float4 p = tile[k]; float Rj = tileR[k];
                FARPAIR(0) FARPAIR(1)
            }
        } else {
            #pragma unroll 4
            for (int k = 0; k < TJ; k++) {
                float4 p = tile[k]; float Rj = tileR[k];
                PAIR(0) PAIR(1)
            }
        }
    } else {
        if (c == 1) {
            #pragma unroll 4
            for (int k = 0; k < TJ; k++) {
                float4 p = tile[k]; float Rj = tileR[k];
                PAIR(0)
            }
        }
        // Diagonal row c (lane-dependent trips -> branchless term).
        float nxd = (c == 0) ? nx0 : nx1;
        float nyd = (c == 0) ? ny0 : ny1;
        float nzd = (c == 0) ? nz0 : nz1;
        float Rid = (c == 0) ? Ri0 : Ri1;
        for (int k = t + 1; k < TJ; k++) {
            float4 p = tile[k];
            float Rj = tileR[k];
            float d2 = fmaf(nzd, p.z, fmaf(nyd, p.y, fmaf(nxd, p.x, Rid + Rj)));
            accD = fmaf(p.w, term_d2(d2), accD);
        }
    }

    float qd = (c >= ITILE) ? 0.0f : (c == 0) ? qi0 : qi1;
    float accT = qi0 * acc0 + qi1 * acc1 + qd * accD;

    #pragma unroll
    for (int off = 16; off > 0; off >>= 1)
        accT += __shfl_down_sync(0xFFFFFFFFu, accT, off);
    if ((t & 31) == 0) warpsum[t >> 5] = accT;
    __syncthreads();

    if (t == 0) {
        float sum = 0.0f;
        #pragma unroll
        for (int w = 0; w < TJ / 32; w++) sum += warpsum[w];
        g_partials[bid] = sum;
        __threadfence();
        int ticket = atomicAdd(&g_counter, 1);
        lastFlag = (ticket == nBlocks - 1) ? 1 : 0;
    }
    __syncthreads();

    if (lastFlag) {
        float a2 = 0.0f;
        for (int i = t; i < nBlocks; i += TJ)
            a2 += g_partials[i];
        #pragma unroll
        for (int off = 16; off > 0; off >>= 1)
            a2 += __shfl_down_sync(0xFFFFFFFFu, a2, off);
        if ((t & 31) == 0) warpsum[t >> 5] = a2;
        __syncthreads();
        if (t == 0) {
            float sum = 0.0f;
            #pragma unroll
            for (int w = 0; w < TJ / 32; w++) sum += warpsum[w];
            out[0] = sum * 332.0637f;
            g_counter = 0;
        }
    }
}

extern "C" void kernel_launch(void* const* d_in, const int* in_sizes, int n_in,
                              void* d_out, int out_size) {
    const float* q   = (const float*)d_in[0];
    const float* xyz = (const float*)d_in[1];
    float* out = (float*)d_out;

    int n = in_sizes[0];
    if (n > MAXN) n = MAXN;
    int nChunks = (n + CHUNK - 1) / CHUNK;
    int jT = (n + TJ - 1) / TJ;
    int iT = (n + TI - 1) / TI;

    int nBlocks = 0;
    for (int d = 0; d < jT; d++) {
        int cnt = (jT - 1 - d) / ITILE + 1;
        if (cnt > iT) cnt = iT;
        if (cnt < 1) cnt = 1;
        nBlocks += cnt;
    }
    if (nBlocks > MAX_BLOCKS) nBlocks = MAX_BLOCKS;

    sortA<<<nChunks, CHUNK>>>(xyz, n);
    sortB<<<1, NBINS>>>(nChunks);
    sortC<<<nChunks, CHUNK>>>(q, xyz, n);
    elec_pair_kernel<<<nBlocks, TJ>>>(out, n, jT, iT, nBlocks);
}